// round 15
// baseline (speedup 1.0000x reference)
#include <cuda_runtime.h>
#include <cstdint>
#include <cstddef>

#define BB 2
#define NN 512
#define HH 128
#define DD 128
#define TTT 8
#define ZZ 256

#define TR 64
#define TSB 64          // senders per CTA
#define NSP 8           // number of s-chunks (NN/TSB)
#define ESTRIDE 132
#define FLT_MAX_F 3.402823466e+38f

typedef unsigned long long ull;

// ---------------- packed f32x2 helpers ----------------
__device__ __forceinline__ ull pack2(float x, float y) {
    ull r;
    asm("mov.b64 %0, {%1, %2};" : "=l"(r) : "f"(x), "f"(y));
    return r;
}
__device__ __forceinline__ float2 unpack2(ull v) {
    float2 r;
    asm("mov.b64 {%0, %1}, %2;" : "=f"(r.x), "=f"(r.y) : "l"(v));
    return r;
}
__device__ __forceinline__ void fma2(ull& d, ull a, ull b) {
    asm("fma.rn.f32x2 %0, %1, %2, %3;" : "=l"(d) : "l"(a), "l"(b), "l"(d));
}

// ---------------- device scratch (no allocation allowed) ----------------
__device__ __align__(16) float g_m1 [BB*NN*DD];
__device__ __align__(16) float g_m2f[BB*NN*DD];
__device__ __align__(16) float g_o1 [BB*NN*DD];
__device__ __align__(16) float g_t1 [BB*NN*TTT];
__device__ __align__(16) float g_t2f[BB*NN*TTT];
__device__ __align__(16) float g_gm [BB*DD];
__device__ __align__(16) float g_gt [BB*TTT];
__device__ __align__(16) float g_part[BB*NSP*NN*DD];
// kp-major k-pair packed weights: g_Wkp[kp*128 + d] = (W[2kp][d], W[2kp+1][d])
__device__ __align__(16) ull g_Wkp[64*128];
__device__ __align__(16) ull g_Wtp[64*TTT];

// ---------------- kG: graph projections ----------------
__global__ void FALR3_kG(const float* __restrict__ graph,
                         const float* __restrict__ Wmg, const float* __restrict__ bmg,
                         const float* __restrict__ bme,
                         const float* __restrict__ Wtg, const float* __restrict__ btg,
                         const float* __restrict__ bte) {
    int b = blockIdx.x, t = threadIdx.x;
    __shared__ float g[HH];
    g[t] = graph[b*HH + t];
    __syncthreads();
    float a = 0.f;
#pragma unroll 8
    for (int k = 0; k < HH; k++) a += g[k] * Wmg[k*DD + t];
    g_gm[b*DD + t] = a + bmg[t] + bme[t];
    if (t < TTT) {
        float a2 = 0.f;
#pragma unroll 8
        for (int k = 0; k < HH; k++) a2 += g[k] * Wtg[k*TTT + t];
        g_gt[b*TTT + t] = a2 + btg[t] + bte[t];
    }
}

// ---------------- kA: per-node projections ----------------
__global__ void FALR3_kA(const float* __restrict__ node, const float* __restrict__ hidden,
                         const float* __restrict__ Wm1, const float* __restrict__ bm1,
                         const float* __restrict__ Wm2, const float* __restrict__ bm2,
                         const float* __restrict__ Wo1, const float* __restrict__ bo1,
                         const float* __restrict__ bo2,
                         const float* __restrict__ Wt1, const float* __restrict__ bt1,
                         const float* __restrict__ Wt2, const float* __restrict__ bt2) {
    int row0 = blockIdx.x * 8, t = threadIdx.x;
    int b = row0 / NN;
    __shared__ float z[8][ZZ];
#pragma unroll
    for (int r = 0; r < 8; r++) {
        z[r][t]      = node  [(row0 + r)*HH + t];
        z[r][HH + t] = hidden[(row0 + r)*HH + t];
    }
    __syncthreads();
    float a1[8], a2[8], a3[8];
#pragma unroll
    for (int r = 0; r < 8; r++) { a1[r] = 0.f; a2[r] = 0.f; a3[r] = 0.f; }
    for (int k = 0; k < ZZ; k++) {
        float w1 = Wm1[k*DD + t], w2 = Wm2[k*DD + t], w3 = Wo1[k*DD + t];
#pragma unroll
        for (int r = 0; r < 8; r++) {
            float zk = z[r][k];
            a1[r] += zk * w1; a2[r] += zk * w2; a3[r] += zk * w3;
        }
    }
    float gm = g_gm[b*DD + t];
#pragma unroll
    for (int r = 0; r < 8; r++) {
        int row = row0 + r;
        g_m1 [row*DD + t] = a1[r] + bm1[t];
        g_m2f[row*DD + t] = a2[r] + bm2[t] + gm;
        g_o1 [row*DD + t] = a3[r] + bo1[t] + bo2[t];
    }
    if (t < 2*TTT) {
        int tt = t & 7; bool second = (t >= TTT);
        const float* W = second ? Wt2 : Wt1;
        float a[8];
#pragma unroll
        for (int r = 0; r < 8; r++) a[r] = 0.f;
        for (int k = 0; k < ZZ; k++) {
            float w = W[k*TTT + tt];
#pragma unroll
            for (int r = 0; r < 8; r++) a[r] += z[r][k] * w;
        }
        if (!second) {
#pragma unroll
            for (int r = 0; r < 8; r++) g_t1[(row0 + r)*TTT + tt] = a[r] + bt1[tt];
        } else {
            float gt = g_gt[b*TTT + tt];
#pragma unroll
            for (int r = 0; r < 8; r++) g_t2f[(row0 + r)*TTT + tt] = a[r] + bt2[tt] + gt;
        }
    }
}

// ---------------- kW: build kp-major k-pair packed weight tables ------------
__global__ void FALR3_kW(const float* __restrict__ Wme, const float* __restrict__ Wte) {
    int tid = blockIdx.x * blockDim.x + threadIdx.x;
    int nth = gridDim.x * blockDim.x;
    for (int i = tid; i < 64*128; i += nth) {
        int kp = i >> 7, d = i & 127;
        g_Wkp[i] = pack2(Wme[(2*kp)*DD + d], Wme[(2*kp + 1)*DD + d]);
    }
    for (int i = tid; i < 64*TTT; i += nth) {
        int kp = i >> 3, c = i & 7;
        g_Wtp[i] = pack2(Wte[(2*kp)*TTT + c], Wte[(2*kp + 1)*TTT + c]);
    }
}

// ---------------- kB: fused edge GEMM + tri + masked max (k-pair FFMA2) ----
// grid (NSP, NN/TR, BB) = (8,8,2) = 128 CTAs, 512 threads, 1 wave, 16 warps/SM.
// Thread map: tx = tid&127 -> col tx ; ty = tid>>7 (0..3) -> rows ty*16..+15.
__global__ __launch_bounds__(512, 1) void FALR3_kB(
        const float* __restrict__ edge, const float* __restrict__ adj,
        float* __restrict__ out_tri) {
    __shared__ __align__(16) float Es[TR*ESTRIDE];
    __shared__ __align__(16) ull   Wts[64*TTT];    // tri pairs, kp-major [kp*8+c]
    __shared__ __align__(16) float t1s[TR*TTT];
    __shared__ __align__(16) float m2s[128];
    __shared__ __align__(16) float adjs[TR];
    __shared__ __align__(16) float t2s[TTT];

    int tid = threadIdx.x;
    int b = blockIdx.z, r0 = blockIdx.y * TR, s0 = blockIdx.x * TSB;
    int tx = tid & 127, ty = tid >> 7;
    int row0 = ty * 16;

    for (int i = tid; i < 64*TTT; i += 512) Wts[i] = g_Wtp[i];
    for (int i = tid; i < TR*TTT;  i += 512) t1s[i] = g_t1[(b*NN + r0)*TTT + i];

    float A[16];
    float Zr[16];
#pragma unroll
    for (int i = 0; i < 16; i++) { A[i] = -FLT_MAX_F; Zr[i] = -FLT_MAX_F; }

    for (int si = 0; si < TSB; si++) {
        int s = s0 + si;
        __syncthreads();   // protect smem from previous-iter consumers
        const float4* esrc = (const float4*)(edge + ((size_t)((b*NN + s)*NN + r0)) * HH);
#pragma unroll
        for (int v = tid; v < TR*32; v += 512) {
            float4 f = esrc[v];
            int row = v >> 5, c = v & 31;
            *(float4*)&Es[row*ESTRIDE + c*4] = f;
        }
        if (tid < 128)            m2s[tid]        = g_m2f[(b*NN + s)*DD + tid];
        else if (tid < 128 + TR)  adjs[tid-128]   = adj[(size_t)(b*NN + s)*NN + r0 + (tid - 128)];
        else if (tid < 136 + TR)  t2s[tid-128-TR] = g_t2f[(b*NN + s)*TTT + (tid - 128 - TR)];
        __syncthreads();

        // GEMM: one column per thread; lanes of acc2 = (even-k, odd-k) partials
        ull acc2[16];
#pragma unroll
        for (int i = 0; i < 16; i++) acc2[i] = 0ULL;

        for (int k = 0; k < 128; k += 4) {
            int kp = k >> 1;
            ull w0 = g_Wkp[kp*128 + tx];          // coalesced 256B/warp
            ull w1 = g_Wkp[(kp + 1)*128 + tx];
#pragma unroll
            for (int i = 0; i < 16; i++) {
                longlong2 ev = *(const longlong2*)&Es[(row0 + i)*ESTRIDE + k];
                fma2(acc2[i], (ull)ev.x, w0);
                fma2(acc2[i], (ull)ev.y, w1);
            }
        }

        // triplet messages: 512 threads = 64 rows x 8 cols, 1 output each
        {
            int trow = tid >> 3, tc = tid & 7;
            ull at = 0ULL;
#pragma unroll 8
            for (int k = 0; k < 128; k += 4) {
                int kp = k >> 1;
                longlong2 ev = *(const longlong2*)&Es[trow*ESTRIDE + k];
                ull w0 = Wts[kp*TTT + tc];
                ull w1 = Wts[(kp + 1)*TTT + tc];
                fma2(at, (ull)ev.x, w0);
                fma2(at, (ull)ev.y, w1);
            }
            float2 ap = unpack2(at);
            float tv = fmaxf(ap.x + ap.y + t1s[trow*TTT + tc] + t2s[tc], 0.f);
            out_tri[((size_t)((b*NN + s)*NN) + r0 + trow)*TTT + tc] = tv;
        }

        // masked running max (m1 deferred to block end)
        float m2v = m2s[tx];
#pragma unroll
        for (int i = 0; i < 16; i++) {
            float ad = adjs[row0 + i];
            bool on = (ad != 0.f);
            if (!on) Zr[i] = 0.f;
            float2 p = unpack2(acc2[i]);
            float t0 = p.x + p.y + m2v;
            A[i] = fmaxf(A[i], on ? t0 : -FLT_MAX_F);
        }
    }

    // block end: fold in m1, combine zero-presence, store partial tile
    float* pbase = &g_part[((size_t)(b*NSP + blockIdx.x)*NN + r0)*DD];
#pragma unroll
    for (int i = 0; i < 16; i++) {
        int row = row0 + i;
        float m1v = g_m1[(size_t)(b*NN + r0 + row)*DD + tx];
        pbase[row*DD + tx] = fmaxf(A[i] + m1v, Zr[i]);
    }
}

// ---------------- kC: reduce partials, ret = o1f + msgs@Wo2 ----------------
__global__ void FALR3_kC(const float* __restrict__ Wo2, float* __restrict__ out) {
    int row0 = blockIdx.x * 2, t = threadIdx.x;
    int b = row0 / NN;
    int rn0 = row0 - b*NN;
    __shared__ float ms[2][DD];
#pragma unroll
    for (int r = 0; r < 2; r++) {
        float m = -FLT_MAX_F;
#pragma unroll
        for (int p = 0; p < NSP; p++)
            m = fmaxf(m, g_part[((size_t)(b*NSP + p)*NN + rn0 + r)*DD + t]);
        ms[r][t] = m;
    }
    __syncthreads();
    float acc0 = 0.f, acc1 = 0.f;
    for (int k = 0; k < DD; k++) {
        float w = Wo2[k*DD + t];
        acc0 += ms[0][k] * w;
        acc1 += ms[1][k] * w;
    }
    out[(row0 + 0)*DD + t] = acc0 + g_o1[(row0 + 0)*DD + t];
    out[(row0 + 1)*DD + t] = acc1 + g_o1[(row0 + 1)*DD + t];
}

// ---------------- launch ----------------
extern "C" void kernel_launch(void* const* d_in, const int* in_sizes, int n_in,
                              void* d_out, int out_size) {
    const float* node  = (const float*)d_in[0];
    const float* edge  = (const float*)d_in[1];
    const float* graph = (const float*)d_in[2];
    const float* adj   = (const float*)d_in[3];
    const float* hidden= (const float*)d_in[4];
    const float* Wm1 = (const float*)d_in[5];  const float* bm1 = (const float*)d_in[6];
    const float* Wm2 = (const float*)d_in[7];  const float* bm2 = (const float*)d_in[8];
    const float* Wme = (const float*)d_in[9];  const float* bme = (const float*)d_in[10];
    const float* Wmg = (const float*)d_in[11]; const float* bmg = (const float*)d_in[12];
    const float* Wo1 = (const float*)d_in[13]; const float* bo1 = (const float*)d_in[14];
    const float* Wo2 = (const float*)d_in[15]; const float* bo2 = (const float*)d_in[16];
    const float* Wt1 = (const float*)d_in[17]; const float* bt1 = (const float*)d_in[18];
    const float* Wt2 = (const float*)d_in[19]; const float* bt2 = (const float*)d_in[20];
    const float* Wte = (const float*)d_in[21]; const float* bte = (const float*)d_in[22];
    const float* Wtg = (const float*)d_in[23]; const float* btg = (const float*)d_in[24];

    float* out     = (float*)d_out;
    float* out_ret = out;                       // [B,N,D]
    float* out_tri = out + BB*NN*DD;            // [B,N,N,T]

    FALR3_kG<<<BB, 128>>>(graph, Wmg, bmg, bme, Wtg, btg, bte);
    FALR3_kA<<<BB*NN/8, 128>>>(node, hidden, Wm1, bm1, Wm2, bm2,
                               Wo1, bo1, bo2, Wt1, bt1, Wt2, bt2);
    FALR3_kW<<<32, 256>>>(Wme, Wte);

    dim3 gB(NSP, NN/TR, BB);   // (8, 8, 2) = 128 CTAs
    FALR3_kB<<<gB, 512>>>(edge, adj, out_tri);

    FALR3_kC<<<BB*NN/2, 128>>>(Wo2, out_ret);
}

// round 16
// speedup vs baseline: 1.2328x; 1.2328x over previous
#include <cuda_runtime.h>
#include <cstdint>
#include <cstddef>

#define BB 2
#define NN 512
#define HH 128
#define DD 128
#define TTT 8
#define ZZ 256

#define TR 64
#define TSB 64          // senders per CTA
#define NSP 8           // number of s-chunks (NN/TSB)
#define ESTRIDE 132
#define FLT_MAX_F 3.402823466e+38f

typedef unsigned long long ull;

// ---------------- packed f32x2 helpers ----------------
__device__ __forceinline__ ull pack2(float x, float y) {
    ull r;
    asm("mov.b64 %0, {%1, %2};" : "=l"(r) : "f"(x), "f"(y));
    return r;
}
__device__ __forceinline__ float2 unpack2(ull v) {
    float2 r;
    asm("mov.b64 {%0, %1}, %2;" : "=f"(r.x), "=f"(r.y) : "l"(v));
    return r;
}
__device__ __forceinline__ void fma2(ull& d, ull a, ull b) {
    asm("fma.rn.f32x2 %0, %1, %2, %3;" : "=l"(d) : "l"(a), "l"(b), "l"(d));
}

// ---------------- device scratch (no allocation allowed) ----------------
__device__ __align__(16) float g_m1 [BB*NN*DD];
__device__ __align__(16) float g_m2f[BB*NN*DD];
__device__ __align__(16) float g_o1 [BB*NN*DD];
__device__ __align__(16) float g_t1 [BB*NN*TTT];
__device__ __align__(16) float g_t2f[BB*NN*TTT];
__device__ __align__(16) float g_gm [BB*DD];
__device__ __align__(16) float g_gt [BB*TTT];
__device__ __align__(16) float g_part[BB*NSP*NN*DD];
// kp-major k-pair packed weights: g_Wkp[kp*128 + d] = (W[2kp][d], W[2kp+1][d])
__device__ __align__(16) ull g_Wkp[64*128];
__device__ __align__(16) ull g_Wtp[64*TTT];

// ---------------- kG: graph projections ----------------
__global__ void FALR3_kG(const float* __restrict__ graph,
                         const float* __restrict__ Wmg, const float* __restrict__ bmg,
                         const float* __restrict__ bme,
                         const float* __restrict__ Wtg, const float* __restrict__ btg,
                         const float* __restrict__ bte) {
    int b = blockIdx.x, t = threadIdx.x;
    __shared__ float g[HH];
    g[t] = graph[b*HH + t];
    __syncthreads();
    float a = 0.f;
#pragma unroll 8
    for (int k = 0; k < HH; k++) a += g[k] * Wmg[k*DD + t];
    g_gm[b*DD + t] = a + bmg[t] + bme[t];
    if (t < TTT) {
        float a2 = 0.f;
#pragma unroll 8
        for (int k = 0; k < HH; k++) a2 += g[k] * Wtg[k*TTT + t];
        g_gt[b*TTT + t] = a2 + btg[t] + bte[t];
    }
}

// ---------------- kA: per-node projections ----------------
__global__ void FALR3_kA(const float* __restrict__ node, const float* __restrict__ hidden,
                         const float* __restrict__ Wm1, const float* __restrict__ bm1,
                         const float* __restrict__ Wm2, const float* __restrict__ bm2,
                         const float* __restrict__ Wo1, const float* __restrict__ bo1,
                         const float* __restrict__ bo2,
                         const float* __restrict__ Wt1, const float* __restrict__ bt1,
                         const float* __restrict__ Wt2, const float* __restrict__ bt2) {
    int row0 = blockIdx.x * 8, t = threadIdx.x;
    int b = row0 / NN;
    __shared__ float z[8][ZZ];
#pragma unroll
    for (int r = 0; r < 8; r++) {
        z[r][t]      = node  [(row0 + r)*HH + t];
        z[r][HH + t] = hidden[(row0 + r)*HH + t];
    }
    __syncthreads();
    float a1[8], a2[8], a3[8];
#pragma unroll
    for (int r = 0; r < 8; r++) { a1[r] = 0.f; a2[r] = 0.f; a3[r] = 0.f; }
    for (int k = 0; k < ZZ; k++) {
        float w1 = Wm1[k*DD + t], w2 = Wm2[k*DD + t], w3 = Wo1[k*DD + t];
#pragma unroll
        for (int r = 0; r < 8; r++) {
            float zk = z[r][k];
            a1[r] += zk * w1; a2[r] += zk * w2; a3[r] += zk * w3;
        }
    }
    float gm = g_gm[b*DD + t];
#pragma unroll
    for (int r = 0; r < 8; r++) {
        int row = row0 + r;
        g_m1 [row*DD + t] = a1[r] + bm1[t];
        g_m2f[row*DD + t] = a2[r] + bm2[t] + gm;
        g_o1 [row*DD + t] = a3[r] + bo1[t] + bo2[t];
    }
    if (t < 2*TTT) {
        int tt = t & 7; bool second = (t >= TTT);
        const float* W = second ? Wt2 : Wt1;
        float a[8];
#pragma unroll
        for (int r = 0; r < 8; r++) a[r] = 0.f;
        for (int k = 0; k < ZZ; k++) {
            float w = W[k*TTT + tt];
#pragma unroll
            for (int r = 0; r < 8; r++) a[r] += z[r][k] * w;
        }
        if (!second) {
#pragma unroll
            for (int r = 0; r < 8; r++) g_t1[(row0 + r)*TTT + tt] = a[r] + bt1[tt];
        } else {
            float gt = g_gt[b*TTT + tt];
#pragma unroll
            for (int r = 0; r < 8; r++) g_t2f[(row0 + r)*TTT + tt] = a[r] + bt2[tt] + gt;
        }
    }
}

// ---------------- kW: build kp-major k-pair packed weight tables ------------
__global__ void FALR3_kW(const float* __restrict__ Wme, const float* __restrict__ Wte) {
    int tid = blockIdx.x * blockDim.x + threadIdx.x;
    int nth = gridDim.x * blockDim.x;
    for (int i = tid; i < 64*128; i += nth) {
        int kp = i >> 7, d = i & 127;
        g_Wkp[i] = pack2(Wme[(2*kp)*DD + d], Wme[(2*kp + 1)*DD + d]);
    }
    for (int i = tid; i < 64*TTT; i += nth) {
        int kp = i >> 3, c = i & 7;
        g_Wtp[i] = pack2(Wte[(2*kp)*TTT + c], Wte[(2*kp + 1)*TTT + c]);
    }
}

// ---------------- kB: fused edge GEMM + tri + masked max (k-pair FFMA2) ----
// grid (NSP, NN/TR, BB) = (8,8,2) = 128 CTAs, 512 threads, 1 wave, 16 warps/SM.
// Thread map: tx = tid&63 -> cols 2tx,2tx+1 ; ty = tid>>6 (0..7) -> rows ty*8..+7.
// Balanced traffic optimum: E wf = 512*R, W wf = 32768/R, min at R=8 (C=2).
__global__ __launch_bounds__(512, 1) void FALR3_kB(
        const float* __restrict__ edge, const float* __restrict__ adj,
        float* __restrict__ out_tri) {
    __shared__ __align__(16) float Es[TR*ESTRIDE];
    __shared__ __align__(16) ull   Wts[64*TTT];    // tri pairs, kp-major [kp*8+c]
    __shared__ __align__(16) float t1s[TR*TTT];
    __shared__ __align__(16) float m2s[128];
    __shared__ __align__(16) float adjs[TR];
    __shared__ __align__(16) float t2s[TTT];

    int tid = threadIdx.x;
    int b = blockIdx.z, r0 = blockIdx.y * TR, s0 = blockIdx.x * TSB;
    int tx = tid & 63, ty = tid >> 6;
    int col = tx * 2;
    int row0 = ty * 8;

    for (int i = tid; i < 64*TTT; i += 512) Wts[i] = g_Wtp[i];
    for (int i = tid; i < TR*TTT;  i += 512) t1s[i] = g_t1[(b*NN + r0)*TTT + i];

    float A[8][2];
    float Zr[8];
#pragma unroll
    for (int i = 0; i < 8; i++) {
        A[i][0] = -FLT_MAX_F; A[i][1] = -FLT_MAX_F; Zr[i] = -FLT_MAX_F;
    }

    for (int si = 0; si < TSB; si++) {
        int s = s0 + si;
        __syncthreads();   // protect smem from previous-iter consumers
        const float4* esrc = (const float4*)(edge + ((size_t)((b*NN + s)*NN + r0)) * HH);
#pragma unroll
        for (int v = tid; v < TR*32; v += 512) {
            float4 f = esrc[v];
            int row = v >> 5, c = v & 31;
            *(float4*)&Es[row*ESTRIDE + c*4] = f;
        }
        if (tid < 128)            m2s[tid]        = g_m2f[(b*NN + s)*DD + tid];
        else if (tid < 128 + TR)  adjs[tid-128]   = adj[(size_t)(b*NN + s)*NN + r0 + (tid - 128)];
        else if (tid < 136 + TR)  t2s[tid-128-TR] = g_t2f[(b*NN + s)*TTT + (tid - 128 - TR)];
        __syncthreads();

        // GEMM: 8 rows x 2 cols per thread; acc lanes = (even-k, odd-k) partials
        ull acc2[8][2];
#pragma unroll
        for (int i = 0; i < 8; i++) { acc2[i][0] = 0ULL; acc2[i][1] = 0ULL; }

#pragma unroll 8
        for (int k = 0; k < 128; k += 4) {
            int kp = k >> 1;
            // coalesced 512B/warp per load
            longlong2 w0 = *(const longlong2*)&g_Wkp[kp*128 + col];        // kp: (c0,c0+1)
            longlong2 w1 = *(const longlong2*)&g_Wkp[(kp + 1)*128 + col];  // kp+1
#pragma unroll
            for (int i = 0; i < 8; i++) {
                longlong2 ev = *(const longlong2*)&Es[(row0 + i)*ESTRIDE + k]; // broadcast
                fma2(acc2[i][0], (ull)ev.x, (ull)w0.x);
                fma2(acc2[i][1], (ull)ev.x, (ull)w0.y);
                fma2(acc2[i][0], (ull)ev.y, (ull)w1.x);
                fma2(acc2[i][1], (ull)ev.y, (ull)w1.y);
            }
        }

        // triplet messages: 512 threads = 64 rows x 8 cols, 1 output each
        {
            int trow = tid >> 3, tc = tid & 7;
            ull at = 0ULL;
#pragma unroll 8
            for (int k = 0; k < 128; k += 4) {
                int kp = k >> 1;
                longlong2 ev = *(const longlong2*)&Es[trow*ESTRIDE + k];
                ull w0 = Wts[kp*TTT + tc];
                ull w1 = Wts[(kp + 1)*TTT + tc];
                fma2(at, (ull)ev.x, w0);
                fma2(at, (ull)ev.y, w1);
            }
            float2 ap = unpack2(at);
            float tv = fmaxf(ap.x + ap.y + t1s[trow*TTT + tc] + t2s[tc], 0.f);
            out_tri[((size_t)((b*NN + s)*NN) + r0 + trow)*TTT + tc] = tv;
        }

        // masked running max (m1 deferred to block end)
        float2 m2v = *(const float2*)&m2s[col];
#pragma unroll
        for (int i = 0; i < 8; i++) {
            float ad = adjs[row0 + i];
            bool on = (ad != 0.f);
            if (!on) Zr[i] = 0.f;
            float2 p0 = unpack2(acc2[i][0]);
            float2 p1 = unpack2(acc2[i][1]);
            float t0 = p0.x + p0.y + m2v.x;
            float t1 = p1.x + p1.y + m2v.y;
            A[i][0] = fmaxf(A[i][0], on ? t0 : -FLT_MAX_F);
            A[i][1] = fmaxf(A[i][1], on ? t1 : -FLT_MAX_F);
        }
    }

    // block end: fold in m1, combine zero-presence, store partial tile
    float* pbase = &g_part[((size_t)(b*NSP + blockIdx.x)*NN + r0)*DD];
#pragma unroll
    for (int i = 0; i < 8; i++) {
        int row = row0 + i;
        float2 m1v = *(const float2*)&g_m1[(size_t)(b*NN + r0 + row)*DD + col];
        float2 ov;
        ov.x = fmaxf(A[i][0] + m1v.x, Zr[i]);
        ov.y = fmaxf(A[i][1] + m1v.y, Zr[i]);
        *(float2*)&pbase[row*DD + col] = ov;
    }
}

// ---------------- kC: reduce partials, ret = o1f + msgs@Wo2 ----------------
__global__ void FALR3_kC(const float* __restrict__ Wo2, float* __restrict__ out) {
    int row0 = blockIdx.x * 2, t = threadIdx.x;
    int b = row0 / NN;
    int rn0 = row0 - b*NN;
    __shared__ float ms[2][DD];
#pragma unroll
    for (int r = 0; r < 2; r++) {
        float m = -FLT_MAX_F;
#pragma unroll
        for (int p = 0; p < NSP; p++)
            m = fmaxf(m, g_part[((size_t)(b*NSP + p)*NN + rn0 + r)*DD + t]);
        ms[r][t] = m;
    }
    __syncthreads();
    float acc0 = 0.f, acc1 = 0.f;
    for (int k = 0; k < DD; k++) {
        float w = Wo2[k*DD + t];
        acc0 += ms[0][k] * w;
        acc1 += ms[1][k] * w;
    }
    out[(row0 + 0)*DD + t] = acc0 + g_o1[(row0 + 0)*DD + t];
    out[(row0 + 1)*DD + t] = acc1 + g_o1[(row0 + 1)*DD + t];
}

// ---------------- launch ----------------
extern "C" void kernel_launch(void* const* d_in, const int* in_sizes, int n_in,
                              void* d_out, int out_size) {
    const float* node  = (const float*)d_in[0];
    const float* edge  = (const float*)d_in[1];
    const float* graph = (const float*)d_in[2];
    const float* adj   = (const float*)d_in[3];
    const float* hidden= (const float*)d_in[4];
    const float* Wm1 = (const float*)d_in[5];  const float* bm1 = (const float*)d_in[6];
    const float* Wm2 = (const float*)d_in[7];  const float* bm2 = (const float*)d_in[8];
    const float* Wme = (const float*)d_in[9];  const float* bme = (const float*)d_in[10];
    const float* Wmg = (const float*)d_in[11]; const float* bmg = (const float*)d_in[12];
    const float* Wo1 = (const float*)d_in[13]; const float* bo1 = (const float*)d_in[14];
    const float* Wo2 = (const float*)d_in[15]; const float* bo2 = (const float*)d_in[16];
    const float* Wt1 = (const float*)d_in[17]; const float* bt1 = (const float*)d_in[18];
    const float* Wt2 = (const float*)d_in[19]; const float* bt2 = (const float*)d_in[20];
    const float* Wte = (const float*)d_in[21]; const float* bte = (const float*)d_in[22];
    const float* Wtg = (const float*)d_in[23]; const float* btg = (const float*)d_in[24];

    float* out     = (float*)d_out;
    float* out_ret = out;                       // [B,N,D]
    float* out_tri = out + BB*NN*DD;            // [B,N,N,T]

    FALR3_kG<<<BB, 128>>>(graph, Wmg, bmg, bme, Wtg, btg, bte);
    FALR3_kA<<<BB*NN/8, 128>>>(node, hidden, Wm1, bm1, Wm2, bm2,
                               Wo1, bo1, bo2, Wt1, bt1, Wt2, bt2);
    FALR3_kW<<<32, 256>>>(Wme, Wte);

    dim3 gB(NSP, NN/TR, BB);   // (8, 8, 2) = 128 CTAs
    FALR3_kB<<<gB, 512>>>(edge, adj, out_tri);

    FALR3_kC<<<BB*NN/2, 128>>>(Wo2, out_ret);
}